// round 14
// baseline (speedup 1.0000x reference)
#include <cuda_runtime.h>
#include <cuda_fp16.h>
#include <cstdint>

// Problem constants (fixed by setup_inputs)
#define BATCH 128
#define IC    2048
#define OC    32
#define OD    16
#define ROW   512          // OC*OD floats per (b,i) row
#define THREADS 256
#define WPB   8            // warps per block
#define BPB_I 8            // blocks per batch, init pass
#define BPB_T 32           // blocks per batch, iter passes (grid 4096)
#define IPW_I 32           // rows per warp, init
#define IPW_T 8            // rows per warp, iter
#define DEPTH 4            // smem staging ring depth (rows)

typedef unsigned long long u64;
#define LOG2E_F 1.4426950408889634f

// Scratch (device globals: allocation-free per harness rules)
__device__ __align__(16) __half g_u16[(size_t)BATCH * IC * ROW];    // 268 MB fp16 copy of u
__device__ __align__(16) float  g_part[(size_t)BATCH * BPB_T * ROW];// 8 MB block partials
__device__ __align__(16) float  g_vsum[(size_t)BATCH * ROW];        // 256 KB running v sum
__device__ int g_cnt[BATCH];                                        // zero-init; self-resetting

__device__ __forceinline__ void cp_async16(unsigned saddr, const void* gptr) {
    asm volatile("cp.async.cg.shared.global [%0], [%1], 16;\n"
                 :: "r"(saddr), "l"(gptr) : "memory");
}
__device__ __forceinline__ u64 pack_f2(float lo, float hi) {
    u64 r; asm("mov.b64 %0, {%1, %2};" : "=l"(r) : "f"(lo), "f"(hi)); return r;
}
__device__ __forceinline__ void unpack_f2(u64 v, float& lo, float& hi) {
    asm("mov.b64 {%0, %1}, %2;" : "=f"(lo), "=f"(hi) : "l"(v));
}
__device__ __forceinline__ void ffma2(u64& d, u64 a, u64 b) {
    asm("fma.rn.f32x2 %0, %1, %2, %0;" : "+l"(d) : "l"(a), "l"(b));
}
__device__ __forceinline__ float ex2a(float x) {
    float y; asm("ex2.approx.f32 %0, %1;" : "=f"(y) : "f"(x)); return y;
}
__device__ __forceinline__ float rcpa(float x) {
    float y; asm("rcp.approx.f32 %0, %1;" : "=f"(y) : "f"(x)); return y;
}

// Cross-block reduction + squash, after warp partials are in sred.
// NB = chunks per batch. mode 0: vsum = v; mode 1: vsum += v; mode 2: out = v.
template<int NB>
__device__ __forceinline__ void block_tail_reduce(float (*sred)[ROW], int b, int chunk,
                                                  int mode, float* __restrict__ out)
{
    __shared__ bool amLast;
    const int t = threadIdx.x;
    float r0 = 0.f, r1 = 0.f;
    #pragma unroll
    for (int w = 0; w < WPB; ++w) { r0 += sred[w][t]; r1 += sred[w][t + 256]; }
    float* bp = g_part + ((size_t)b * NB + chunk) * ROW;
    bp[t] = r0; bp[t + 256] = r1;

    __threadfence();
    __syncthreads();
    if (t == 0) {
        int old = atomicAdd(&g_cnt[b], 1);
        amLast = (old == NB - 1);
        if (amLast) g_cnt[b] = 0;      // replay-safe reset
    }
    __syncthreads();
    if (!amLast) return;
    __threadfence();                   // acquire: see all blocks' partials

    const float* pb = g_part + (size_t)b * NB * ROW;
    float s0 = 0.f, s1 = 0.f;
    #pragma unroll 8
    for (int c = 0; c < NB; ++c) {     // fixed order -> deterministic
        s0 += pb[(size_t)c * ROW + t];
        s1 += pb[(size_t)c * ROW + t + 256];
    }

    // squash: ||s||^2 over the 16 d-lanes of each o
    const unsigned FULL = 0xffffffffu;
    float q0 = s0 * s0, q1 = s1 * s1;
    #pragma unroll
    for (int m = 1; m < 16; m <<= 1) {
        q0 += __shfl_xor_sync(FULL, q0, m);
        q1 += __shfl_xor_sync(FULL, q1, m);
    }
    float v0 = s0 * sqrtf(q0) / (1.f + q0);
    float v1 = s1 * sqrtf(q1) / (1.f + q1);

    float* vs = g_vsum + (size_t)b * ROW;
    if (mode == 0)      { vs[t] = v0;            vs[t + 256] = v1; }
    else if (mode == 1) { vs[t] += v0;           vs[t + 256] += v1; }
    else                { out[(size_t)b * ROW + t] = v0;
                          out[(size_t)b * ROW + t + 256] = v1; }
}

// Init pass: c = softmax(b_in), s = sum_i c*u; emits fp16 copy of u.
// HBM-bound (804 MB) at ~7.4 TB/s — unchanged.
__global__ __launch_bounds__(THREADS)
void rba_init(const float* __restrict__ u, const float* __restrict__ bin)
{
    __shared__ float sred[WPB][ROW];
    const int b     = blockIdx.x >> 3;
    const int chunk = blockIdx.x & 7;
    const int warp  = threadIdx.x >> 5;
    const int lane  = threadIdx.x & 31;
    const int g     = lane >> 2;
    const int wc    = chunk * WPB + warp;
    const unsigned FULL = 0xffffffffu;

    float4 acc[4];
    #pragma unroll
    for (int j = 0; j < 4; ++j) acc[j] = make_float4(0.f, 0.f, 0.f, 0.f);

    const size_t ubase = ((size_t)b * IC + (size_t)wc * IPW_I) * ROW;

    for (int ii = 0; ii < IPW_I; ++ii) {
        const int i = wc * IPW_I + ii;
        const float4* up = reinterpret_cast<const float4*>(u + ubase + (size_t)ii * ROW);
        __half* dst = g_u16 + ubase + (size_t)ii * ROW;

        float4 u4[4];
        #pragma unroll
        for (int j = 0; j < 4; ++j) u4[j] = up[j * 32 + lane];   // coalesced 2KB/row

        #pragma unroll
        for (int j = 0; j < 4; ++j) {
            union { uint2 raw; __half2 h[2]; } pk;
            pk.h[0] = __floats2half2_rn(u4[j].x, u4[j].y);
            pk.h[1] = __floats2half2_rn(u4[j].z, u4[j].w);
            *reinterpret_cast<uint2*>(dst + j * 128 + lane * 4) = pk.raw;
        }

        float bv = bin[(size_t)i * OC + lane];
        float logit[4];
        #pragma unroll
        for (int j = 0; j < 4; ++j) logit[j] = __shfl_sync(FULL, bv, j * 8 + g);

        float e[4], Z = 0.f;
        #pragma unroll
        for (int j = 0; j < 4; ++j) { e[j] = __expf(logit[j]); Z += e[j]; }
        Z += __shfl_xor_sync(FULL, Z, 4);
        Z += __shfl_xor_sync(FULL, Z, 8);
        Z += __shfl_xor_sync(FULL, Z, 16);
        float rZ = __frcp_rn(Z);
        #pragma unroll
        for (int j = 0; j < 4; ++j) {
            float c = e[j] * rZ;
            acc[j].x += c * u4[j].x; acc[j].y += c * u4[j].y;
            acc[j].z += c * u4[j].z; acc[j].w += c * u4[j].w;
        }
    }

    #pragma unroll
    for (int j = 0; j < 4; ++j)
        *reinterpret_cast<float4*>(&sred[warp][j * 128 + lane * 4]) = acc[j];
    __syncthreads();
    block_tail_reduce<BPB_I>(sred, b, chunk, /*mode=*/0, nullptr);
}

// Agreement pass: logits = bin + dot(u, vsum); c = softmax; s = sum_i c*u.
// LANE = OUTPUT CAP layout: lane l owns all 16 d's of o=l (contiguous 32B of
// the fp16 row) -> in-lane dot (no shuffles), ONE exp per lane, 5-shuffle
// butterfly for the softmax normalizer, one coalesced prior LDG per row.
// fp16 u via cp.async 4-row smem ring; packed f32x2 FMA; serpentine FLIP;
// 4 blocks/SM.
template<int MODE, int FLIP>
__global__ __launch_bounds__(THREADS, 4)
void rba_iter(const float* __restrict__ bin, float* __restrict__ out)
{
    __shared__ __align__(16) char smem_raw[WPB * DEPTH * ROW * 2];   // 32 KB
    __half (*stage)[DEPTH][ROW] = reinterpret_cast<__half(*)[DEPTH][ROW]>(smem_raw);
    float  (*sred)[ROW]         = reinterpret_cast<float(*)[ROW]>(smem_raw);

    const int bid   = FLIP ? (BATCH * BPB_T - 1 - blockIdx.x) : blockIdx.x;
    const int b     = bid >> 5;                // BPB_T = 32
    const int chunk = bid & 31;
    const int warp  = threadIdx.x >> 5;
    const int lane  = threadIdx.x & 31;        // = output cap o
    const int wc    = chunk * WPB + warp;      // 0..255
    const unsigned FULL = 0xffffffffu;

    // vsum for o=lane: 16 floats, packed & pre-scaled by log2(e)
    u64 vp[8];
    {
        const float* vb = g_vsum + (size_t)b * ROW + lane * 16;
        #pragma unroll
        for (int k = 0; k < 4; ++k) {
            float4 t = *reinterpret_cast<const float4*>(vb + 4 * k);
            vp[2*k]   = pack_f2(t.x * LOG2E_F, t.y * LOG2E_F);
            vp[2*k+1] = pack_f2(t.z * LOG2E_F, t.w * LOG2E_F);
        }
    }

    u64 acc[8];
    #pragma unroll
    for (int k = 0; k < 8; ++k) acc[k] = 0ull;

    const __half* up = g_u16 + ((size_t)b * IC + (size_t)wc * IPW_T) * ROW;
    const float* binp = bin + (size_t)(wc * IPW_T) * OC + lane;
    const int loff = lane * 16;                // halves (32B per lane)

    const unsigned sbase =
        (unsigned)__cvta_generic_to_shared(&stage[warp][0][0]) + loff * 2;

    // prologue: rows 0..2 in flight (3 groups)
    #pragma unroll
    for (int p = 0; p < 3; ++p) {
        const __half* g = up + (size_t)p * ROW + loff;
        cp_async16(sbase + p * (ROW * 2), g);
        cp_async16(sbase + p * (ROW * 2) + 16, g + 8);
        asm volatile("cp.async.commit_group;\n" ::: "memory");
    }

    #pragma unroll
    for (int ii = 0; ii < IPW_T; ++ii) {
        // logit prior for (row ii, o=lane): one coalesced LDG, L2-resident
        float bv = binp[ii * OC];

        const int pf = ii + 3;
        if (pf < IPW_T) {
            const __half* g = up + (size_t)pf * ROW + loff;
            const unsigned sa = sbase + (pf & (DEPTH - 1)) * (ROW * 2);
            cp_async16(sa, g);
            cp_async16(sa + 16, g + 8);
        }
        asm volatile("cp.async.commit_group;\n" ::: "memory");
        asm volatile("cp.async.wait_group 3;\n" ::: "memory");   // row ii ready

        const int s = ii & (DEPTH - 1);
        uint4 r0 = *reinterpret_cast<const uint4*>(&stage[warp][s][loff]);
        uint4 r1 = *reinterpret_cast<const uint4*>(&stage[warp][s][loff + 8]);

        u64 uP[8];
        {
            const __half2* h0 = reinterpret_cast<const __half2*>(&r0);
            const __half2* h1 = reinterpret_cast<const __half2*>(&r1);
            #pragma unroll
            for (int k = 0; k < 4; ++k) {
                float2 f0 = __half22float2(h0[k]);
                float2 f1 = __half22float2(h1[k]);
                uP[k]     = pack_f2(f0.x, f0.y);
                uP[4 + k] = pack_f2(f1.x, f1.y);
            }
        }

        // in-lane dot over 16 d's: two parallel f32x2 chains, no shuffles
        u64 d0 = 0ull, d1 = 0ull;
        #pragma unroll
        for (int k = 0; k < 4; ++k) { ffma2(d0, uP[k], vp[k]); ffma2(d1, uP[4+k], vp[4+k]); }
        float al, ah, bl, bh;
        unpack_f2(d0, al, ah); unpack_f2(d1, bl, bh);
        float p = (al + ah) + (bl + bh);

        float e = ex2a(fmaf(bv, LOG2E_F, p));
        // softmax normalizer: full 32-lane butterfly (each lane = distinct o)
        float Z = e;
        Z += __shfl_xor_sync(FULL, Z, 1);
        Z += __shfl_xor_sync(FULL, Z, 2);
        Z += __shfl_xor_sync(FULL, Z, 4);
        Z += __shfl_xor_sync(FULL, Z, 8);
        Z += __shfl_xor_sync(FULL, Z, 16);
        float c = e * rcpa(Z);
        u64 cp2 = pack_f2(c, c);

        #pragma unroll
        for (int k = 0; k < 8; ++k) ffma2(acc[k], cp2, uP[k]);
    }

    asm volatile("cp.async.wait_group 0;\n" ::: "memory");
    __syncthreads();                       // stage dead; safe to alias as sred

    // warp partial s[o=lane][d] -> sred[warp][lane*16 + d]
    float aa[16];
    #pragma unroll
    for (int k = 0; k < 8; ++k) unpack_f2(acc[k], aa[2*k], aa[2*k+1]);
    float* w0 = &sred[warp][lane * 16];
    #pragma unroll
    for (int k = 0; k < 4; ++k)
        *reinterpret_cast<float4*>(w0 + 4*k) =
            make_float4(aa[4*k], aa[4*k+1], aa[4*k+2], aa[4*k+3]);
    __syncthreads();
    block_tail_reduce<BPB_T>(sred, b, chunk, MODE, out);
}

extern "C" void kernel_launch(void* const* d_in, const int* in_sizes, int n_in,
                              void* d_out, int out_size)
{
    const float* u   = (const float*)d_in[0];  // [128,2048,32,16] f32
    const float* bin = (const float*)d_in[1];  // [2048,32] f32
    float* out = (float*)d_out;                // [128,32,16] f32

    // init writes u16 ascending; serpentine iters alternate direction so each
    // pass starts on the previous pass's L2-resident tail.
    rba_init<<<BATCH * BPB_I, THREADS>>>(u, bin);
    // iter1 (reversed): logits = bin + u.v0          ; vsum += v1
    rba_iter<1, 1><<<BATCH * BPB_T, THREADS>>>(bin, out);
    // iter2 (forward) : logits = bin + u.(v0+v1)     ; vsum += v2
    rba_iter<1, 0><<<BATCH * BPB_T, THREADS>>>(bin, out);
    // iter3 (reversed): logits = bin + u.(v0+v1+v2)  ; out = v3
    rba_iter<2, 1><<<BATCH * BPB_T, THREADS>>>(bin, out);

    (void)in_sizes; (void)n_in; (void)out_size;
}

// round 15
// speedup vs baseline: 1.0626x; 1.0626x over previous
#include <cuda_runtime.h>
#include <cuda_fp16.h>
#include <cstdint>

// Problem constants (fixed by setup_inputs)
#define BATCH 128
#define IC    2048
#define OC    32
#define OD    16
#define ROW   512          // OC*OD floats per (b,i) row
#define THREADS 256
#define WPB   8            // warps per block
#define BPB_I 8            // blocks per batch, init pass
#define BPB_T 32           // blocks per batch, iter passes (grid 4096)
#define IPW_I 32           // rows per warp, init
#define IPW_T 8            // rows per warp, iter
#define DEPTH 6            // smem staging ring depth (rows); 4 rows in flight
#define AHEAD 4            // prefetch distance (rows)

typedef unsigned long long u64;
#define LOG2E_F 1.4426950408889634f

// Scratch (device globals: allocation-free per harness rules)
__device__ __align__(16) __half g_u16[(size_t)BATCH * IC * ROW];    // 268 MB fp16 copy of u
__device__ __align__(16) float  g_part[(size_t)BATCH * BPB_T * ROW];// 8 MB block partials
__device__ __align__(16) float  g_vsum[(size_t)BATCH * ROW];        // 256 KB running v sum
__device__ int g_cnt[BATCH];                                        // zero-init; self-resetting

__device__ __forceinline__ void cp_async16(unsigned saddr, const void* gptr) {
    asm volatile("cp.async.cg.shared.global [%0], [%1], 16;\n"
                 :: "r"(saddr), "l"(gptr) : "memory");
}
__device__ __forceinline__ u64 pack_f2(float lo, float hi) {
    u64 r; asm("mov.b64 %0, {%1, %2};" : "=l"(r) : "f"(lo), "f"(hi)); return r;
}
__device__ __forceinline__ void unpack_f2(u64 v, float& lo, float& hi) {
    asm("mov.b64 {%0, %1}, %2;" : "=f"(lo), "=f"(hi) : "l"(v));
}
__device__ __forceinline__ void ffma2(u64& d, u64 a, u64 b) {
    asm("fma.rn.f32x2 %0, %1, %2, %0;" : "+l"(d) : "l"(a), "l"(b));
}
__device__ __forceinline__ float ex2a(float x) {
    float y; asm("ex2.approx.f32 %0, %1;" : "=f"(y) : "f"(x)); return y;
}
__device__ __forceinline__ float rcpa(float x) {
    float y; asm("rcp.approx.f32 %0, %1;" : "=f"(y) : "f"(x)); return y;
}

// Cross-block reduction + squash, after warp partials are in sred.
// NB = chunks per batch. mode 0: vsum = v; mode 1: vsum += v; mode 2: out = v.
template<int NB>
__device__ __forceinline__ void block_tail_reduce(float (*sred)[ROW], int b, int chunk,
                                                  int mode, float* __restrict__ out)
{
    __shared__ bool amLast;
    const int t = threadIdx.x;
    float r0 = 0.f, r1 = 0.f;
    #pragma unroll
    for (int w = 0; w < WPB; ++w) { r0 += sred[w][t]; r1 += sred[w][t + 256]; }
    float* bp = g_part + ((size_t)b * NB + chunk) * ROW;
    bp[t] = r0; bp[t + 256] = r1;

    __threadfence();
    __syncthreads();
    if (t == 0) {
        int old = atomicAdd(&g_cnt[b], 1);
        amLast = (old == NB - 1);
        if (amLast) g_cnt[b] = 0;      // replay-safe reset
    }
    __syncthreads();
    if (!amLast) return;
    __threadfence();                   // acquire: see all blocks' partials

    const float* pb = g_part + (size_t)b * NB * ROW;
    float s0 = 0.f, s1 = 0.f;
    #pragma unroll 8
    for (int c = 0; c < NB; ++c) {     // fixed order -> deterministic
        s0 += pb[(size_t)c * ROW + t];
        s1 += pb[(size_t)c * ROW + t + 256];
    }

    // squash: ||s||^2 over the 16 d-lanes of each o
    const unsigned FULL = 0xffffffffu;
    float q0 = s0 * s0, q1 = s1 * s1;
    #pragma unroll
    for (int m = 1; m < 16; m <<= 1) {
        q0 += __shfl_xor_sync(FULL, q0, m);
        q1 += __shfl_xor_sync(FULL, q1, m);
    }
    float v0 = s0 * sqrtf(q0) / (1.f + q0);
    float v1 = s1 * sqrtf(q1) / (1.f + q1);

    float* vs = g_vsum + (size_t)b * ROW;
    if (mode == 0)      { vs[t] = v0;            vs[t + 256] = v1; }
    else if (mode == 1) { vs[t] += v0;           vs[t + 256] += v1; }
    else                { out[(size_t)b * ROW + t] = v0;
                          out[(size_t)b * ROW + t + 256] = v1; }
}

// Init pass: c = softmax(b_in), s = sum_i c*u; emits fp16 copy of u.
// HBM-bound (804 MB) near the wall — unchanged.
__global__ __launch_bounds__(THREADS)
void rba_init(const float* __restrict__ u, const float* __restrict__ bin)
{
    __shared__ float sred[WPB][ROW];
    const int b     = blockIdx.x >> 3;
    const int chunk = blockIdx.x & 7;
    const int warp  = threadIdx.x >> 5;
    const int lane  = threadIdx.x & 31;
    const int g     = lane >> 2;
    const int wc    = chunk * WPB + warp;
    const unsigned FULL = 0xffffffffu;

    float4 acc[4];
    #pragma unroll
    for (int j = 0; j < 4; ++j) acc[j] = make_float4(0.f, 0.f, 0.f, 0.f);

    const size_t ubase = ((size_t)b * IC + (size_t)wc * IPW_I) * ROW;

    for (int ii = 0; ii < IPW_I; ++ii) {
        const int i = wc * IPW_I + ii;
        const float4* up = reinterpret_cast<const float4*>(u + ubase + (size_t)ii * ROW);
        __half* dst = g_u16 + ubase + (size_t)ii * ROW;

        float4 u4[4];
        #pragma unroll
        for (int j = 0; j < 4; ++j) u4[j] = up[j * 32 + lane];   // coalesced 2KB/row

        #pragma unroll
        for (int j = 0; j < 4; ++j) {
            union { uint2 raw; __half2 h[2]; } pk;
            pk.h[0] = __floats2half2_rn(u4[j].x, u4[j].y);
            pk.h[1] = __floats2half2_rn(u4[j].z, u4[j].w);
            *reinterpret_cast<uint2*>(dst + j * 128 + lane * 4) = pk.raw;
        }

        float bv = bin[(size_t)i * OC + lane];
        float logit[4];
        #pragma unroll
        for (int j = 0; j < 4; ++j) logit[j] = __shfl_sync(FULL, bv, j * 8 + g);

        float e[4], Z = 0.f;
        #pragma unroll
        for (int j = 0; j < 4; ++j) { e[j] = __expf(logit[j]); Z += e[j]; }
        Z += __shfl_xor_sync(FULL, Z, 4);
        Z += __shfl_xor_sync(FULL, Z, 8);
        Z += __shfl_xor_sync(FULL, Z, 16);
        float rZ = __frcp_rn(Z);
        #pragma unroll
        for (int j = 0; j < 4; ++j) {
            float c = e[j] * rZ;
            acc[j].x += c * u4[j].x; acc[j].y += c * u4[j].y;
            acc[j].z += c * u4[j].z; acc[j].w += c * u4[j].w;
        }
    }

    #pragma unroll
    for (int j = 0; j < 4; ++j)
        *reinterpret_cast<float4*>(&sred[warp][j * 128 + lane * 4]) = acc[j];
    __syncthreads();
    block_tail_reduce<BPB_I>(sred, b, chunk, /*mode=*/0, nullptr);
}

// Agreement pass (R12 structure, deeper pipeline): logits = bin + dot(u,vsum);
// c = softmax; s = sum_i c*u. fp16 u via cp.async 6-slot ring, 4 rows in
// flight (2KB/warp; 48KB/SM at 32 warps >= latency-BW product). Base-2
// exponentials; packed f32x2 FMA; serpentine FLIP; 4 blocks/SM.
template<int MODE, int FLIP>
__global__ __launch_bounds__(THREADS, 4)
void rba_iter(const float* __restrict__ bin, float* __restrict__ out)
{
    __shared__ __align__(16) char smem_raw[WPB * DEPTH * ROW * 2];   // 48 KB
    __half (*stage)[DEPTH][ROW] = reinterpret_cast<__half(*)[DEPTH][ROW]>(smem_raw);
    float  (*sred)[ROW]         = reinterpret_cast<float(*)[ROW]>(smem_raw);

    const int bid   = FLIP ? (BATCH * BPB_T - 1 - blockIdx.x) : blockIdx.x;
    const int b     = bid >> 5;                // BPB_T = 32
    const int chunk = bid & 31;
    const int warp  = threadIdx.x >> 5;
    const int lane  = threadIdx.x & 31;
    const int wc    = chunk * WPB + warp;      // 0..255
    const unsigned FULL = 0xffffffffu;

    // vsum packed & pre-scaled by log2(e): slot A floats [8*lane,+8), slot B +256
    u64 vpA[4], vpB[4];
    {
        const float* vb = g_vsum + (size_t)b * ROW + lane * 8;
        float4 a0 = *reinterpret_cast<const float4*>(vb);
        float4 a1 = *reinterpret_cast<const float4*>(vb + 4);
        float4 b0 = *reinterpret_cast<const float4*>(vb + 256);
        float4 b1 = *reinterpret_cast<const float4*>(vb + 260);
        vpA[0] = pack_f2(a0.x*LOG2E_F, a0.y*LOG2E_F); vpA[1] = pack_f2(a0.z*LOG2E_F, a0.w*LOG2E_F);
        vpA[2] = pack_f2(a1.x*LOG2E_F, a1.y*LOG2E_F); vpA[3] = pack_f2(a1.z*LOG2E_F, a1.w*LOG2E_F);
        vpB[0] = pack_f2(b0.x*LOG2E_F, b0.y*LOG2E_F); vpB[1] = pack_f2(b0.z*LOG2E_F, b0.w*LOG2E_F);
        vpB[2] = pack_f2(b1.x*LOG2E_F, b1.y*LOG2E_F); vpB[3] = pack_f2(b1.z*LOG2E_F, b1.w*LOG2E_F);
    }

    u64 accA[4], accB[4];
    #pragma unroll
    for (int k = 0; k < 4; ++k) { accA[k] = 0ull; accB[k] = 0ull; }

    const __half* up = g_u16 + ((size_t)b * IC + (size_t)wc * IPW_T) * ROW;
    const float* bp0 = bin + (size_t)(wc * IPW_T) * OC + (lane >> 1);
    const int loff = lane * 8;                 // halves

    const unsigned sbase =
        (unsigned)__cvta_generic_to_shared(&stage[warp][0][0]) + loff * 2;

    // prologue: rows 0..AHEAD-1 in flight (AHEAD groups)
    #pragma unroll
    for (int p = 0; p < AHEAD; ++p) {
        const __half* g = up + (size_t)p * ROW + loff;
        cp_async16(sbase + p * (ROW * 2), g);
        cp_async16(sbase + p * (ROW * 2) + 512, g + 256);
        asm volatile("cp.async.commit_group;\n" ::: "memory");
    }

    #pragma unroll
    for (int ii = 0; ii < IPW_T; ++ii) {
        // raw logit priors (L1/L2-resident; log2e folded into fmaf below)
        float bvA = bp0[ii * OC];
        float bvB = bp0[ii * OC + 16];

        const int pf = ii + AHEAD;
        if (pf < IPW_T) {
            const __half* g = up + (size_t)pf * ROW + loff;
            const unsigned sa = sbase + (pf % DEPTH) * (ROW * 2);
            cp_async16(sa, g);
            cp_async16(sa + 512, g + 256);
        }
        asm volatile("cp.async.commit_group;\n" ::: "memory");
        asm volatile("cp.async.wait_group 4;\n" ::: "memory");   // row ii ready

        const int s = ii % DEPTH;
        uint4 rA = *reinterpret_cast<const uint4*>(&stage[warp][s][loff]);
        uint4 rB = *reinterpret_cast<const uint4*>(&stage[warp][s][256 + loff]);

        u64 uPA[4], uPB[4];
        {
            const __half2* hA = reinterpret_cast<const __half2*>(&rA);
            const __half2* hB = reinterpret_cast<const __half2*>(&rB);
            #pragma unroll
            for (int k = 0; k < 4; ++k) {
                float2 fa = __half22float2(hA[k]);
                float2 fb = __half22float2(hB[k]);
                uPA[k] = pack_f2(fa.x, fa.y);
                uPB[k] = pack_f2(fb.x, fb.y);
            }
        }

        // packed dots (pre-scaled by log2e via v)
        u64 dA = 0ull, dB = 0ull;
        #pragma unroll
        for (int k = 0; k < 4; ++k) { ffma2(dA, uPA[k], vpA[k]); ffma2(dB, uPB[k], vpB[k]); }
        float xl, xh;
        unpack_f2(dA, xl, xh); float pA = xl + xh;
        unpack_f2(dB, xl, xh); float pB = xl + xh;
        pA += __shfl_xor_sync(FULL, pA, 1);   // full d-dot within lane pair
        pB += __shfl_xor_sync(FULL, pB, 1);

        float eA = ex2a(fmaf(bvA, LOG2E_F, pA));
        float eB = ex2a(fmaf(bvB, LOG2E_F, pB));
        float Z  = eA + eB;
        // xor{2,4,8,16} sums each of the 32 output caps exactly once
        Z += __shfl_xor_sync(FULL, Z, 2);
        Z += __shfl_xor_sync(FULL, Z, 4);
        Z += __shfl_xor_sync(FULL, Z, 8);
        Z += __shfl_xor_sync(FULL, Z, 16);
        float rZ = rcpa(Z);
        u64 cAp = pack_f2(eA * rZ, eA * rZ);
        u64 cBp = pack_f2(eB * rZ, eB * rZ);

        #pragma unroll
        for (int k = 0; k < 4; ++k) { ffma2(accA[k], cAp, uPA[k]); ffma2(accB[k], cBp, uPB[k]); }
    }

    asm volatile("cp.async.wait_group 0;\n" ::: "memory");
    __syncthreads();                       // stage dead; safe to alias as sred

    float aa[8], bb[8];
    #pragma unroll
    for (int k = 0; k < 4; ++k) {
        unpack_f2(accA[k], aa[2*k], aa[2*k+1]);
        unpack_f2(accB[k], bb[2*k], bb[2*k+1]);
    }
    float* w0 = &sred[warp][lane * 8];
    *reinterpret_cast<float4*>(w0)       = make_float4(aa[0], aa[1], aa[2], aa[3]);
    *reinterpret_cast<float4*>(w0 + 4)   = make_float4(aa[4], aa[5], aa[6], aa[7]);
    *reinterpret_cast<float4*>(w0 + 256) = make_float4(bb[0], bb[1], bb[2], bb[3]);
    *reinterpret_cast<float4*>(w0 + 260) = make_float4(bb[4], bb[5], bb[6], bb[7]);
    __syncthreads();
    block_tail_reduce<BPB_T>(sred, b, chunk, MODE, out);
}

extern "C" void kernel_launch(void* const* d_in, const int* in_sizes, int n_in,
                              void* d_out, int out_size)
{
    const float* u   = (const float*)d_in[0];  // [128,2048,32,16] f32
    const float* bin = (const float*)d_in[1];  // [2048,32] f32
    float* out = (float*)d_out;                // [128,32,16] f32

    // init writes u16 ascending; serpentine iters alternate direction so each
    // pass starts on the previous pass's L2-resident tail.
    rba_init<<<BATCH * BPB_I, THREADS>>>(u, bin);
    // iter1 (reversed): logits = bin + u.v0          ; vsum += v1
    rba_iter<1, 1><<<BATCH * BPB_T, THREADS>>>(bin, out);
    // iter2 (forward) : logits = bin + u.(v0+v1)     ; vsum += v2
    rba_iter<1, 0><<<BATCH * BPB_T, THREADS>>>(bin, out);
    // iter3 (reversed): logits = bin + u.(v0+v1+v2)  ; out = v3
    rba_iter<2, 1><<<BATCH * BPB_T, THREADS>>>(bin, out);

    (void)in_sizes; (void)n_in; (void)out_size;
}